// round 6
// baseline (speedup 1.0000x reference)
#include <cuda_runtime.h>
#include <cstdint>

#define N_PED 131072
#define D_IN 256
#define D_OUT 128
#define SEGSZ 64
#define N_SEQ 2048

namespace {
constexpr int H_ST = D_OUT + 4;   // 132: conflict-free A-frag (4lr+lc) and ctx B-frag (4lc+lr)
constexpr int X_ST = 64 + 4;      // 68:  conflict-free A-frag, float4-aligned rows
constexpr int S_ST = 64 + 4;      // 68

constexpr int OFF_W = 0;                          // W fragment layout: 32768 floats exact
constexpr int OFF_B = OFF_W + D_IN * D_OUT;       // 32768
constexpr int OFF_H = OFF_B + D_OUT;              // 32896
constexpr int OFF_X = OFF_H + SEGSZ * H_ST;       // 41344 (byte 165376, 16B aligned)
// Ss overlays Xs: phase-disjoint (Xs dead after GEMM mainloop, Ss born after epilogue sync)
constexpr int OFF_S = OFF_X;
constexpr int SMEM_FLOATS = OFF_X + SEGSZ * X_ST; // 45696
constexpr int SMEM_BYTES = SMEM_FLOATS * 4;       // 182784 B < 227 KB
} // namespace

__device__ __forceinline__ float tf32r(float x) {
    uint32_t u = __float_as_uint(x);
    asm("cvt.rna.tf32.f32 %0, %1;" : "=r"(u) : "r"(u));
    return __uint_as_float(u);
}

__device__ __forceinline__ void mma8(float* d, const uint32_t* a, const uint32_t* b) {
    asm volatile(
        "mma.sync.aligned.m16n8k8.row.col.f32.tf32.tf32.f32 "
        "{%0,%1,%2,%3}, {%4,%5,%6,%7}, {%8,%9}, {%0,%1,%2,%3};\n"
        : "+f"(d[0]), "+f"(d[1]), "+f"(d[2]), "+f"(d[3])
        : "r"(a[0]), "r"(a[1]), "r"(a[2]), "r"(a[3]), "r"(b[0]), "r"(b[1]));
}

__global__ __launch_bounds__(512, 1)
void attn_hidden_kernel(const float* __restrict__ Xall,
                        const float* __restrict__ Wg,
                        const float* __restrict__ bg,
                        float* __restrict__ out)
{
    extern __shared__ float smem[];
    float*  Wf = smem + OFF_W;   // fragment layout: [k8(32)][ng(16)][lane(32)][2]
    float*  bs = smem + OFF_B;
    float*  hs = smem + OFF_H;
    float*  Xs = smem + OFF_X;
    float*  Ss = smem + OFF_S;   // alias of Xs

    const int tid  = threadIdx.x;
    const int warp = tid >> 5;
    const int lane = tid & 31;
    const int lr   = lane >> 2;
    const int lc   = lane & 3;

    // 4x4 warp grid (16 warps)
    const int mq = warp & 3;       // m tile: 16 rows
    const int nq = warp >> 2;      // n tile: 32 cols (GEMM/ctx), 16 cols (S)
    const int m0  = mq * 16;
    const int n0  = nq * 32;
    const int n0s = nq * 16;

    // ---- Build W in MMA B-fragment layout (tf32-rounded), once per CTA ----
    // Wf[(k8*16 + ng)*32 + lane] (float2): {W[k8*8+lc][ng*8+lr], W[k8*8+lc+4][ng*8+lr]}
    for (int i = tid; i < 32 * 16 * 32; i += 512) {
        int k8i = i >> 9;
        int ng  = (i >> 5) & 15;
        int ln  = i & 31;
        int row = k8i * 8 + (ln & 3);
        int col = ng * 8 + (ln >> 2);
        float2 v = make_float2(tf32r(Wg[row * D_OUT + col]),
                               tf32r(Wg[(row + 4) * D_OUT + col]));
        reinterpret_cast<float2*>(Wf)[i] = v;
    }
    if (tid < D_OUT) bs[tid] = bg[tid];
    __syncthreads();

    for (int g = blockIdx.x; g < N_SEQ; g += gridDim.x) {
        const float* Xg = Xall + (size_t)g * SEGSZ * D_IN;

        // ================= GEMM: h = X(64x256) @ W(256x128) =================
        float acc[4][4];
        #pragma unroll
        for (int nt = 0; nt < 4; ++nt)
            #pragma unroll
            for (int i = 0; i < 4; ++i) acc[nt][i] = 0.f;

        // prefetch chunk 0 (8 floats/thread)
        float4 pre[2];
        #pragma unroll
        for (int t = 0; t < 2; ++t) {
            int idx = tid + t * 512;
            int row = idx >> 4, q = idx & 15;
            pre[t] = *reinterpret_cast<const float4*>(Xg + row * D_IN + q * 4);
        }

        for (int kc = 0; kc < 4; ++kc) {
            __syncthreads();   // guards Xs reuse (prev chunk / prev segment's Ss reads)
            #pragma unroll
            for (int t = 0; t < 2; ++t) {
                int idx = tid + t * 512;
                int row = idx >> 4, q = idx & 15;
                float4 r4 = make_float4(tf32r(pre[t].x), tf32r(pre[t].y),
                                        tf32r(pre[t].z), tf32r(pre[t].w));
                *reinterpret_cast<float4*>(Xs + row * X_ST + q * 4) = r4;
            }
            __syncthreads();   // Xs ready
            if (kc < 3) {
                #pragma unroll
                for (int t = 0; t < 2; ++t) {
                    int idx = tid + t * 512;
                    int row = idx >> 4, q = idx & 15;
                    pre[t] = *reinterpret_cast<const float4*>(
                        Xg + row * D_IN + (kc + 1) * 64 + q * 4);
                }
            }
            #pragma unroll
            for (int k8 = 0; k8 < 8; ++k8) {
                const int kl = k8 * 8;
                uint32_t af[4];
                {
                    const float* p = Xs + (m0 + lr) * X_ST + kl + lc;
                    af[0] = __float_as_uint(p[0]);
                    af[1] = __float_as_uint(p[8 * X_ST]);
                    af[2] = __float_as_uint(p[4]);
                    af[3] = __float_as_uint(p[8 * X_ST + 4]);
                }
                const int k8g = kc * 8 + k8;
                uint32_t bf[4][2];
                #pragma unroll
                for (int nt = 0; nt < 4; ++nt) {
                    float2 w2 = reinterpret_cast<const float2*>(Wf)
                        [(k8g * 16 + nq * 4 + nt) * 32 + lane];
                    bf[nt][0] = __float_as_uint(w2.x);
                    bf[nt][1] = __float_as_uint(w2.y);
                }
                #pragma unroll
                for (int nt = 0; nt < 4; ++nt)
                    mma8(acc[nt], af, bf[nt]);
            }
        }

        // epilogue: h (+bias), tf32-rounded -> smem
        #pragma unroll
        for (int nt = 0; nt < 4; ++nt) {
            int row = m0 + lr;
            int col = n0 + nt * 8 + 2 * lc;
            hs[row * H_ST + col]           = tf32r(acc[nt][0] + bs[col]);
            hs[row * H_ST + col + 1]       = tf32r(acc[nt][1] + bs[col + 1]);
            hs[(row + 8) * H_ST + col]     = tf32r(acc[nt][2] + bs[col]);
            hs[(row + 8) * H_ST + col + 1] = tf32r(acc[nt][3] + bs[col + 1]);
        }
        __syncthreads();

        // ================= S = h @ h^T  (64x64, K=128) =================
        float accS[2][4];
        #pragma unroll
        for (int nt = 0; nt < 2; ++nt)
            #pragma unroll
            for (int i = 0; i < 4; ++i) accS[nt][i] = 0.f;

        #pragma unroll
        for (int k8 = 0; k8 < 16; ++k8) {
            const int kl = k8 * 8;
            uint32_t af[4];
            {
                const float* p = hs + (m0 + lr) * H_ST + kl + lc;
                af[0] = __float_as_uint(p[0]);
                af[1] = __float_as_uint(p[8 * H_ST]);
                af[2] = __float_as_uint(p[4]);
                af[3] = __float_as_uint(p[8 * H_ST + 4]);
            }
            uint32_t bf[2][2];
            #pragma unroll
            for (int nt = 0; nt < 2; ++nt) {
                const float* p = hs + (n0s + nt * 8 + lr) * H_ST + kl + lc;
                bf[nt][0] = __float_as_uint(p[0]);
                bf[nt][1] = __float_as_uint(p[4]);
            }
            #pragma unroll
            for (int nt = 0; nt < 2; ++nt)
                mma8(accS[nt], af, bf[nt]);
        }
        // store S raw fp32 (into Ss = Xs region; Xs dead, all warps past last kc sync... 
        // ordering: S store happens after this warp's S MMAs which only read hs; other
        // warps still in S MMAs also only read hs -> no race)
        #pragma unroll
        for (int nt = 0; nt < 2; ++nt) {
            int row = m0 + lr;
            int col = n0s + nt * 8 + 2 * lc;
            Ss[row * S_ST + col]           = accS[nt][0];
            Ss[row * S_ST + col + 1]       = accS[nt][1];
            Ss[(row + 8) * S_ST + col]     = accS[nt][2];
            Ss[(row + 8) * S_ST + col + 1] = accS[nt][3];
        }
        __syncthreads();

        // ================= softmax (row-wise), in place, P tf32 =================
        {
            const int srow = tid >> 3;      // 64 rows, 8 threads/row
            const int sq   = tid & 7;       // 8 cols each
            float4* rp = reinterpret_cast<float4*>(Ss + srow * S_ST + sq * 8);
            float v[8];
            {
                float4 t0 = rp[0], t1 = rp[1];
                v[0]=t0.x; v[1]=t0.y; v[2]=t0.z; v[3]=t0.w;
                v[4]=t1.x; v[5]=t1.y; v[6]=t1.z; v[7]=t1.w;
            }
            float m = v[0];
            #pragma unroll
            for (int i = 1; i < 8; ++i) m = fmaxf(m, v[i]);
            m = fmaxf(m, __shfl_xor_sync(0xffffffffu, m, 1));
            m = fmaxf(m, __shfl_xor_sync(0xffffffffu, m, 2));
            m = fmaxf(m, __shfl_xor_sync(0xffffffffu, m, 4));
            float s = 0.f;
            #pragma unroll
            for (int i = 0; i < 8; ++i) { v[i] = __expf(v[i] - m); s += v[i]; }
            s += __shfl_xor_sync(0xffffffffu, s, 1);
            s += __shfl_xor_sync(0xffffffffu, s, 2);
            s += __shfl_xor_sync(0xffffffffu, s, 4);
            const float inv = 1.0f / s;
            rp[0] = make_float4(tf32r(v[0]*inv), tf32r(v[1]*inv),
                                tf32r(v[2]*inv), tf32r(v[3]*inv));
            rp[1] = make_float4(tf32r(v[4]*inv), tf32r(v[5]*inv),
                                tf32r(v[6]*inv), tf32r(v[7]*inv));
        }
        __syncthreads();

        // ================= ctx = P(64x64) @ h(64x128) =================
        #pragma unroll
        for (int nt = 0; nt < 4; ++nt)
            #pragma unroll
            for (int i = 0; i < 4; ++i) acc[nt][i] = 0.f;

        #pragma unroll
        for (int k8 = 0; k8 < 8; ++k8) {
            const int kl = k8 * 8;
            uint32_t af[4];
            {
                const float* p = Ss + (m0 + lr) * S_ST + kl + lc;
                af[0] = __float_as_uint(p[0]);
                af[1] = __float_as_uint(p[8 * S_ST]);
                af[2] = __float_as_uint(p[4]);
                af[3] = __float_as_uint(p[8 * S_ST + 4]);
            }
            uint32_t bf[4][2];
            #pragma unroll
            for (int nt = 0; nt < 4; ++nt) {
                const float* p = hs + (kl + lc) * H_ST + n0 + nt * 8 + lr;
                bf[nt][0] = __float_as_uint(p[0]);
                bf[nt][1] = __float_as_uint(p[4 * H_ST]);
            }
            #pragma unroll
            for (int nt = 0; nt < 4; ++nt)
                mma8(acc[nt], af, bf[nt]);
        }

        // store ctx to gmem
        #pragma unroll
        for (int nt = 0; nt < 4; ++nt) {
            size_t row = (size_t)g * SEGSZ + m0 + lr;
            int col = n0 + nt * 8 + 2 * lc;
            *reinterpret_cast<float2*>(out + row * D_OUT + col) =
                make_float2(acc[nt][0], acc[nt][1]);
            *reinterpret_cast<float2*>(out + (row + 8) * D_OUT + col) =
                make_float2(acc[nt][2], acc[nt][3]);
        }
        // next-iteration kc=0 __syncthreads() guards Xs/Ss overwrite after ctx reads
    }
}

extern "C" void kernel_launch(void* const* d_in, const int* in_sizes, int n_in,
                              void* d_out, int out_size) {
    (void)in_sizes; (void)n_in; (void)out_size;
    const float* X = (const float*)d_in[0];
    const float* W = (const float*)d_in[1];
    const float* b = (const float*)d_in[2];
    float* out = (float*)d_out;

    cudaFuncSetAttribute(attn_hidden_kernel,
                         cudaFuncAttributeMaxDynamicSharedMemorySize, SMEM_BYTES);
    attn_hidden_kernel<<<148, 512, SMEM_BYTES>>>(X, W, b, out);
}

// round 7
// speedup vs baseline: 1.9869x; 1.9869x over previous
#include <cuda_runtime.h>
#include <cstdint>

#define D_IN 256
#define D_OUT 128
#define SEGSZ 64
#define N_SEQ 2048

namespace {
constexpr int H_ST = D_OUT + 4;   // 132: conflict-free A-frag / ctx B-frag loads
constexpr int X_ST = 64 + 4;      // 68
constexpr int S_ST = 64 + 4;      // 68

constexpr int OFF_H = 0;
constexpr int OFF_X = OFF_H + SEGSZ * H_ST;   // 8448
constexpr int OFF_S = OFF_X + SEGSZ * X_ST;   // +4352
constexpr int OFF_B = OFF_S + SEGSZ * S_ST;   // +4352
constexpr int SMEM_FLOATS = OFF_B + D_OUT;    // 17280
constexpr int SMEM_BYTES = SMEM_FLOATS * 4;   // 69120 B -> 2 CTAs/SM easily
} // namespace

// W in MMA B-fragment layout, tf32-rounded:
// g_wfrag[(k8*16 + ng)*32 + lane] = { W[k8*8 + (lane&3)][ng*8 + (lane>>2)],
//                                     W[k8*8 + (lane&3) + 4][ng*8 + (lane>>2)] }
__device__ float2 g_wfrag[32 * 16 * 32];

__device__ __forceinline__ float tf32r(float x) {
    uint32_t u = __float_as_uint(x);
    asm("cvt.rna.tf32.f32 %0, %1;" : "=r"(u) : "r"(u));
    return __uint_as_float(u);
}

__device__ __forceinline__ void mma8(float* d, const uint32_t* a, const uint32_t* b) {
    asm volatile(
        "mma.sync.aligned.m16n8k8.row.col.f32.tf32.tf32.f32 "
        "{%0,%1,%2,%3}, {%4,%5,%6,%7}, {%8,%9}, {%0,%1,%2,%3};\n"
        : "+f"(d[0]), "+f"(d[1]), "+f"(d[2]), "+f"(d[3])
        : "r"(a[0]), "r"(a[1]), "r"(a[2]), "r"(a[3]), "r"(b[0]), "r"(b[1]));
}

__global__ __launch_bounds__(256)
void prep_w_kernel(const float* __restrict__ Wg) {
    int i = blockIdx.x * 256 + threadIdx.x;   // 0..16383
    int k8i = i >> 9;
    int ng  = (i >> 5) & 15;
    int ln  = i & 31;
    int row = k8i * 8 + (ln & 3);
    int col = ng * 8 + (ln >> 2);
    g_wfrag[i] = make_float2(tf32r(Wg[row * D_OUT + col]),
                             tf32r(Wg[(row + 4) * D_OUT + col]));
}

__global__ __launch_bounds__(256, 2)
void attn_hidden_kernel(const float* __restrict__ Xall,
                        const float* __restrict__ bg,
                        float* __restrict__ out)
{
    extern __shared__ float smem[];
    float* hs = smem + OFF_H;
    float* Xs = smem + OFF_X;
    float* Ss = smem + OFF_S;
    float* bs = smem + OFF_B;

    const int tid  = threadIdx.x;
    const int warp = tid >> 5;
    const int lane = tid & 31;
    const int lr   = lane >> 2;
    const int lc   = lane & 3;

    // 2x4 warp grid (R4 layout): GEMM/ctx warp tile = 32 rows x 32 cols
    const int m0  = (warp & 1) * 32;
    const int nq  = warp >> 1;       // 0..3
    const int n0  = nq * 32;
    const int n0s = nq * 16;         // S phase: 32 rows x 16 cols

    const int g = blockIdx.x;        // one CTA per segment
    const float* Xg = Xall + (size_t)g * SEGSZ * D_IN;

    if (tid < D_OUT) bs[tid] = bg[tid];

    // ================= GEMM: h = X(64x256) @ W(256x128) =================
    float acc[2][4][4];
    #pragma unroll
    for (int mt = 0; mt < 2; ++mt)
        #pragma unroll
        for (int nt = 0; nt < 4; ++nt)
            #pragma unroll
            for (int i = 0; i < 4; ++i) acc[mt][nt][i] = 0.f;

    // register ring (depth 2) of B fragments from gmem (L1/L2-resident W)
    uint32_t bfr[2][4][2];
    const float2* __restrict__ wf = g_wfrag;
    #pragma unroll
    for (int nt = 0; nt < 4; ++nt) {
        float2 w2 = __ldg(&wf[(0 * 16 + nq * 4 + nt) * 32 + lane]);
        bfr[0][nt][0] = __float_as_uint(w2.x);
        bfr[0][nt][1] = __float_as_uint(w2.y);
    }

    // prefetch X chunk 0 into regs (16 floats/thread)
    float4 pre[4];
    #pragma unroll
    for (int t = 0; t < 4; ++t) {
        int idx = tid + t * 256;
        int row = idx >> 4, q = idx & 15;
        pre[t] = *reinterpret_cast<const float4*>(Xg + row * D_IN + q * 4);
    }

    #pragma unroll
    for (int kc = 0; kc < 4; ++kc) {
        if (kc > 0) __syncthreads();   // all warps done reading Xs (prev chunk)
        #pragma unroll
        for (int t = 0; t < 4; ++t) {
            int idx = tid + t * 256;
            int row = idx >> 4, q = idx & 15;
            float4 r4 = make_float4(tf32r(pre[t].x), tf32r(pre[t].y),
                                    tf32r(pre[t].z), tf32r(pre[t].w));
            *reinterpret_cast<float4*>(Xs + row * X_ST + q * 4) = r4;
        }
        __syncthreads();               // Xs ready (also covers bs on kc==0)
        if (kc < 3) {
            #pragma unroll
            for (int t = 0; t < 4; ++t) {
                int idx = tid + t * 256;
                int row = idx >> 4, q = idx & 15;
                pre[t] = *reinterpret_cast<const float4*>(
                    Xg + row * D_IN + (kc + 1) * 64 + q * 4);
            }
        }
        #pragma unroll
        for (int k8 = 0; k8 < 8; ++k8) {
            const int k8g = kc * 8 + k8;
            const int cur = k8g & 1;
            // prefetch next k8's B fragments into the other ring slot
            const int nk = (k8g + 1 < 32) ? (k8g + 1) : 31;
            #pragma unroll
            for (int nt = 0; nt < 4; ++nt) {
                float2 w2 = __ldg(&wf[(nk * 16 + nq * 4 + nt) * 32 + lane]);
                bfr[cur ^ 1][nt][0] = __float_as_uint(w2.x);
                bfr[cur ^ 1][nt][1] = __float_as_uint(w2.y);
            }
            const int kl = k8 * 8;
            uint32_t af[2][4];
            #pragma unroll
            for (int mt = 0; mt < 2; ++mt) {
                const float* p = Xs + (m0 + mt * 16 + lr) * X_ST + kl + lc;
                af[mt][0] = __float_as_uint(p[0]);
                af[mt][1] = __float_as_uint(p[8 * X_ST]);
                af[mt][2] = __float_as_uint(p[4]);
                af[mt][3] = __float_as_uint(p[8 * X_ST + 4]);
            }
            #pragma unroll
            for (int mt = 0; mt < 2; ++mt)
                #pragma unroll
                for (int nt = 0; nt < 4; ++nt)
                    mma8(acc[mt][nt], af[mt], bfr[cur][nt]);
        }
    }

    // epilogue: h (+bias), tf32-rounded -> smem
    #pragma unroll
    for (int mt = 0; mt < 2; ++mt) {
        #pragma unroll
        for (int nt = 0; nt < 4; ++nt) {
            int row = m0 + mt * 16 + lr;
            int col = n0 + nt * 8 + 2 * lc;
            hs[row * H_ST + col]           = tf32r(acc[mt][nt][0] + bs[col]);
            hs[row * H_ST + col + 1]       = tf32r(acc[mt][nt][1] + bs[col + 1]);
            hs[(row + 8) * H_ST + col]     = tf32r(acc[mt][nt][2] + bs[col]);
            hs[(row + 8) * H_ST + col + 1] = tf32r(acc[mt][nt][3] + bs[col + 1]);
        }
    }
    __syncthreads();

    // ================= S = h @ h^T  (64x64, K=128) =================
    float accS[2][2][4];
    #pragma unroll
    for (int mt = 0; mt < 2; ++mt)
        #pragma unroll
        for (int nt = 0; nt < 2; ++nt)
            #pragma unroll
            for (int i = 0; i < 4; ++i) accS[mt][nt][i] = 0.f;

    #pragma unroll
    for (int k8 = 0; k8 < 16; ++k8) {
        const int kl = k8 * 8;
        uint32_t af[2][4];
        #pragma unroll
        for (int mt = 0; mt < 2; ++mt) {
            const float* p = hs + (m0 + mt * 16 + lr) * H_ST + kl + lc;
            af[mt][0] = __float_as_uint(p[0]);
            af[mt][1] = __float_as_uint(p[8 * H_ST]);
            af[mt][2] = __float_as_uint(p[4]);
            af[mt][3] = __float_as_uint(p[8 * H_ST + 4]);
        }
        uint32_t bf[2][2];
        #pragma unroll
        for (int nt = 0; nt < 2; ++nt) {
            const float* p = hs + (n0s + nt * 8 + lr) * H_ST + kl + lc;
            bf[nt][0] = __float_as_uint(p[0]);
            bf[nt][1] = __float_as_uint(p[4]);
        }
        #pragma unroll
        for (int mt = 0; mt < 2; ++mt)
            #pragma unroll
            for (int nt = 0; nt < 2; ++nt)
                mma8(accS[mt][nt], af[mt], bf[nt]);
    }
    // store S raw fp32
    #pragma unroll
    for (int mt = 0; mt < 2; ++mt) {
        #pragma unroll
        for (int nt = 0; nt < 2; ++nt) {
            int row = m0 + mt * 16 + lr;
            int col = n0s + nt * 8 + 2 * lc;
            Ss[row * S_ST + col]           = accS[mt][nt][0];
            Ss[row * S_ST + col + 1]       = accS[mt][nt][1];
            Ss[(row + 8) * S_ST + col]     = accS[mt][nt][2];
            Ss[(row + 8) * S_ST + col + 1] = accS[mt][nt][3];
        }
    }
    __syncthreads();

    // ================= softmax (row-wise), in place, P tf32 =================
    {
        const int srow = tid >> 2;      // 64 rows, 4 threads/row
        const int sq   = tid & 3;
        float4* rp = reinterpret_cast<float4*>(Ss + srow * S_ST + sq * 16);
        float v[16];
        #pragma unroll
        for (int j = 0; j < 4; ++j) {
            float4 t = rp[j];
            v[4*j] = t.x; v[4*j+1] = t.y; v[4*j+2] = t.z; v[4*j+3] = t.w;
        }
        float m = v[0];
        #pragma unroll
        for (int i = 1; i < 16; ++i) m = fmaxf(m, v[i]);
        m = fmaxf(m, __shfl_xor_sync(0xffffffffu, m, 1));
        m = fmaxf(m, __shfl_xor_sync(0xffffffffu, m, 2));
        float s = 0.f;
        #pragma unroll
        for (int i = 0; i < 16; ++i) { v[i] = __expf(v[i] - m); s += v[i]; }
        s += __shfl_xor_sync(0xffffffffu, s, 1);
        s += __shfl_xor_sync(0xffffffffu, s, 2);
        const float inv = 1.0f / s;
        #pragma unroll
        for (int j = 0; j < 4; ++j) {
            rp[j] = make_float4(tf32r(v[4*j] * inv),   tf32r(v[4*j+1] * inv),
                                tf32r(v[4*j+2] * inv), tf32r(v[4*j+3] * inv));
        }
    }
    __syncthreads();

    // ================= ctx = P(64x64) @ h(64x128) =================
    #pragma unroll
    for (int mt = 0; mt < 2; ++mt)
        #pragma unroll
        for (int nt = 0; nt < 4; ++nt)
            #pragma unroll
            for (int i = 0; i < 4; ++i) acc[mt][nt][i] = 0.f;

    #pragma unroll
    for (int k8 = 0; k8 < 8; ++k8) {
        const int kl = k8 * 8;
        uint32_t af[2][4];
        #pragma unroll
        for (int mt = 0; mt < 2; ++mt) {
            const float* p = Ss + (m0 + mt * 16 + lr) * S_ST + kl + lc;
            af[mt][0] = __float_as_uint(p[0]);
            af[mt][1] = __float_as_uint(p[8 * S_ST]);
            af[mt][2] = __float_as_uint(p[4]);
            af[mt][3] = __float_as_uint(p[8 * S_ST + 4]);
        }
        uint32_t bf[4][2];
        #pragma unroll
        for (int nt = 0; nt < 4; ++nt) {
            const float* p = hs + (kl + lc) * H_ST + n0 + nt * 8 + lr;
            bf[nt][0] = __float_as_uint(p[0]);
            bf[nt][1] = __float_as_uint(p[4 * H_ST]);
        }
        #pragma unroll
        for (int mt = 0; mt < 2; ++mt)
            #pragma unroll
            for (int nt = 0; nt < 4; ++nt)
                mma8(acc[mt][nt], af[mt], bf[nt]);
    }

    // store ctx to gmem
    #pragma unroll
    for (int mt = 0; mt < 2; ++mt) {
        #pragma unroll
        for (int nt = 0; nt < 4; ++nt) {
            size_t row = (size_t)g * SEGSZ + m0 + mt * 16 + lr;
            int col = n0 + nt * 8 + 2 * lc;
            *reinterpret_cast<float2*>(out + row * D_OUT + col) =
                make_float2(acc[mt][nt][0], acc[mt][nt][1]);
            *reinterpret_cast<float2*>(out + (row + 8) * D_OUT + col) =
                make_float2(acc[mt][nt][2], acc[mt][nt][3]);
        }
    }
}

extern "C" void kernel_launch(void* const* d_in, const int* in_sizes, int n_in,
                              void* d_out, int out_size) {
    (void)in_sizes; (void)n_in; (void)out_size;
    const float* X = (const float*)d_in[0];
    const float* W = (const float*)d_in[1];
    const float* b = (const float*)d_in[2];
    float* out = (float*)d_out;

    prep_w_kernel<<<64, 256>>>(W);   // 16384 fragment float2s

    cudaFuncSetAttribute(attn_hidden_kernel,
                         cudaFuncAttributeMaxDynamicSharedMemorySize, SMEM_BYTES);
    attn_hidden_kernel<<<N_SEQ, 256, SMEM_BYTES>>>(X, b, out);
}